// round 13
// baseline (speedup 1.0000x reference)
#include <cuda_runtime.h>
#include <math_constants.h>
#include <cstdint>

#define BATCH 16
#define SEQ   4096
#define RANKS 8
#define PER   512
#define NTC   512
#define NEG   (-CUDART_INF_F)

__device__ __forceinline__ void st_remote_f32(float* lp, unsigned int r, float v) {
    unsigned int la = (unsigned int)__cvta_generic_to_shared((void*)lp);
    unsigned int ra;
    asm("mapa.shared::cluster.u32 %0, %1, %2;" : "=r"(ra) : "r"(la), "r"(r));
    asm volatile("st.shared::cluster.f32 [%0], %1;" :: "r"(ra), "f"(v) : "memory");
}
__device__ __forceinline__ void st_remote_s32(int* lp, unsigned int r, int v) {
    unsigned int la = (unsigned int)__cvta_generic_to_shared((void*)lp);
    unsigned int ra;
    asm("mapa.shared::cluster.u32 %0, %1, %2;" : "=r"(ra) : "r"(la), "r"(r));
    asm volatile("st.shared::cluster.b32 [%0], %1;" :: "r"(ra), "r"(v) : "memory");
}
// release-arrive on rank r's mbarrier (orders this thread's prior remote stores)
__device__ __forceinline__ void mbar_arrive_remote_rel(unsigned long long* lp, unsigned int r) {
    unsigned int la = (unsigned int)__cvta_generic_to_shared((void*)lp);
    unsigned int ra;
    asm("mapa.shared::cluster.u32 %0, %1, %2;" : "=r"(ra) : "r"(la), "r"(r));
    asm volatile("mbarrier.arrive.release.cluster.shared::cluster.b64 _, [%0];" :: "r"(ra) : "memory");
}
__device__ __forceinline__ void mbar_wait_acq_cluster(unsigned long long* lp, unsigned int parity) {
    unsigned int la = (unsigned int)__cvta_generic_to_shared((void*)lp);
    asm volatile(
        "{\n\t.reg .pred P;\n"
        "WAITLOOP_%=:\n\t"
        "mbarrier.try_wait.parity.acquire.cluster.shared::cta.b64 P, [%0], %1;\n\t"
        "@!P bra WAITLOOP_%=;\n\t}"
        :: "r"(la), "r"(parity) : "memory");
}
#define CLUSTER_SYNC() do { \
    asm volatile("barrier.cluster.arrive.aligned;" ::: "memory"); \
    asm volatile("barrier.cluster.wait.aligned;"   ::: "memory"); } while (0)

__global__ __launch_bounds__(NTC, 1) __cluster_dims__(RANKS, 1, 1)
void pred_head_mb(const float* __restrict__ start_logits,
                  const float* __restrict__ end_logits,
                  float* __restrict__ out) {
    __shared__ float pfx_e[544];   // [0..511] own end-logit prefix; [512..541] next-chunk halo
    __shared__ float sfx_s[544];   // [32..543] own start-logit suffix; [2..31] prev-chunk halo
    __shared__ float redS[16], redE[16];
    __shared__ float wav[16], wav2[16];
    __shared__ int   wai[16], wai2[16];
    __shared__ float wsv[RANKS], wev[RANKS];
    __shared__ int   wsi[RANKS], wei[RANKS];
    __shared__ unsigned long long mbar;

    const int t = threadIdx.x;
    const int lane = t & 31;
    const int wid  = t >> 5;
    unsigned int rank;
    asm("mov.u32 %0, %%cluster_ctarank;" : "=r"(rank));
    const int row = blockIdx.x >> 3;
    const int col = (int)rank * PER + t;
    const float* srow = start_logits + row * SEQ;
    const float* erow = end_logits   + row * SEQ;

    // ---- mbarrier init (rank 0): 7 arrivals expected ----
    if (rank == 0 && t == 0) {
        unsigned int la = (unsigned int)__cvta_generic_to_shared(&mbar);
        asm volatile("mbarrier.init.shared.b64 [%0], %1;" :: "r"(la), "r"(RANKS - 1) : "memory");
    }

    // ---- ALL global loads issued first (cluster sync hides under their latency) ----
    const float sl = srow[col];
    const float el = erow[col];
    const float4* s4r = (const float4*)srow;     // full row for local sums
    const float4* e4r = (const float4*)erow;
    float4 sA = s4r[2 * t], sB = s4r[2 * t + 1];
    float4 eA = e4r[2 * t], eB = e4r[2 * t + 1];
    float hv = 0.f;
    if (wid == 1 && lane < 30)
        hv = (rank > 0) ? srow[(int)rank * PER - 30 + lane] : NEG;
    if (wid == 2 && lane < 30)
        hv = (rank < RANKS - 1) ? erow[((int)rank + 1) * PER + lane] : NEG;

    CLUSTER_SYNC();   // only for mbar-init visibility; overlapped with LDG latency

    // ---- halo scans (log space) ----
    if (wid == 1 && lane < 30) {
        #pragma unroll
        for (int o = 1; o < 32; o <<= 1) {
            float b = __shfl_down_sync(0x3fffffffu, hv, o);
            if (lane + o < 30) hv = fmaxf(hv, b);
        }
        sfx_s[2 + lane] = hv;      // prev-chunk suffix of start-logit
    }
    if (wid == 2 && lane < 30) {
        #pragma unroll
        for (int o = 1; o < 32; o <<= 1) {
            float a = __shfl_up_sync(0x3fffffffu, hv, o);
            if (lane >= o) hv = fmaxf(hv, a);
        }
        pfx_e[512 + lane] = hv;    // next-chunk prefix of end-logit
    }

    // ---- per-warp prefix/suffix maxima on own logits ----
    float pe = el, se_ = el;   // prefix/suffix of end-logit
    float ps_ = sl, ssx = sl;  // prefix/suffix of start-logit
    #pragma unroll
    for (int o = 1; o < 32; o <<= 1) {
        float a = __shfl_up_sync(0xffffffffu, pe, o);    if (lane >= o)     pe  = fmaxf(pe, a);
        float b = __shfl_down_sync(0xffffffffu, se_, o); if (lane + o < 32) se_ = fmaxf(se_, b);
        float c = __shfl_up_sync(0xffffffffu, ps_, o);   if (lane >= o)     ps_ = fmaxf(ps_, c);
        float d = __shfl_down_sync(0xffffffffu, ssx, o); if (lane + o < 32) ssx = fmaxf(ssx, d);
    }
    pfx_e[t] = pe;
    sfx_s[32 + t] = ssx;

    // ---- LOCAL full-row softmax sums (redundant per CTA; zero cross-CTA wait) ----
    float a = ((__expf(sA.x) + __expf(sA.y)) + (__expf(sA.z) + __expf(sA.w)))
            + ((__expf(sB.x) + __expf(sB.y)) + (__expf(sB.z) + __expf(sB.w)));
    float c = ((__expf(eA.x) + __expf(eA.y)) + (__expf(eA.z) + __expf(eA.w)))
            + ((__expf(eB.x) + __expf(eB.y)) + (__expf(eB.z) + __expf(eB.w)));
    #pragma unroll
    for (int o = 16; o; o >>= 1) {
        a += __shfl_xor_sync(0xffffffffu, a, o);
        c += __shfl_xor_sync(0xffffffffu, c, o);
    }
    if (lane == 0) { redS[wid] = a; redE[wid] = c; }

    __syncthreads();   // bar1: scan arrays + halos + sum partials visible

    // ---- width-31 windows via prefix/suffix decomposition (log space) ----
    const float pe30 = __shfl_sync(0xffffffffu, pe, 30);
    const float ss1  = __shfl_sync(0xffffffffu, ssx, 1);
    float F, Bv;
    if (lane == 0)       F = pe30;
    else if (lane == 1)  F = se_;
    else                 F = fmaxf(se_, pfx_e[t + 30]);
    if (lane == 31)      Bv = ss1;
    else if (lane == 30) Bv = ps_;
    else                 Bv = fmaxf(ps_, sfx_s[t + 2]);

    // ---- log-space scores + warp argmax (dual, first-index tie-break) ----
    float bsv = sl + F;  int bsi = col;
    float bev = el + Bv; int bei = col;
    #pragma unroll
    for (int o = 16; o; o >>= 1) {
        float ov = __shfl_xor_sync(0xffffffffu, bsv, o);
        int   oi = __shfl_xor_sync(0xffffffffu, bsi, o);
        if (ov > bsv || (ov == bsv && oi < bsi)) { bsv = ov; bsi = oi; }
        float ov2 = __shfl_xor_sync(0xffffffffu, bev, o);
        int   oi2 = __shfl_xor_sync(0xffffffffu, bei, o);
        if (ov2 > bev || (ov2 == bev && oi2 < bei)) { bev = ov2; bei = oi2; }
    }
    if (lane == 0) { wav[wid] = bsv; wai[wid] = bsi; wav2[wid] = bev; wai2[wid] = bei; }

    // ---- probs: every warp folds the 16 sum partials; STG (no cross-CTA sync) ----
    {
        float v1 = (lane < 16) ? redS[lane] : 0.f;
        float v2 = (lane < 16) ? redE[lane] : 0.f;
        #pragma unroll
        for (int o = 8; o; o >>= 1) {
            v1 += __shfl_xor_sync(0xffffffffu, v1, o);
            v2 += __shfl_xor_sync(0xffffffffu, v2, o);
        }
        const float invS = __frcp_rn(__shfl_sync(0xffffffffu, v1, 0));
        const float invE = __frcp_rn(__shfl_sync(0xffffffffu, v2, 0));
        out[row * SEQ + col]               = __expf(sl) * invS;
        out[BATCH * SEQ + row * SEQ + col] = __expf(el) * invE;
    }

    __syncthreads();   // bar2: warp argmax partials visible

    // ---- warp 1: CTA-level dual winner reduce; push to rank 0 or finalize ----
    if (wid == 1) {
        float v1 = (lane < 16) ? wav[lane]  : NEG;
        int   i1 = (lane < 16) ? wai[lane]  : 0x7fffffff;
        float v2 = (lane < 16) ? wav2[lane] : NEG;
        int   i2 = (lane < 16) ? wai2[lane] : 0x7fffffff;
        #pragma unroll
        for (int o = 8; o; o >>= 1) {
            float ov = __shfl_xor_sync(0xffffffffu, v1, o);
            int   oi = __shfl_xor_sync(0xffffffffu, i1, o);
            if (ov > v1 || (ov == v1 && oi < i1)) { v1 = ov; i1 = oi; }
            float ov2 = __shfl_xor_sync(0xffffffffu, v2, o);
            int   oi2 = __shfl_xor_sync(0xffffffffu, i2, o);
            if (ov2 > v2 || (ov2 == v2 && oi2 < i2)) { v2 = ov2; i2 = oi2; }
        }
        if (rank != 0) {
            if (lane == 0) {
                st_remote_f32(&wsv[rank], 0u, v1);
                st_remote_s32(&wsi[rank], 0u, i1);
                st_remote_f32(&wev[rank], 0u, v2);
                st_remote_s32(&wei[rank], 0u, i2);
                mbar_arrive_remote_rel(&mbar, 0u);   // release: stores land first
            }
            // ranks 1..7 exit — no cluster-wide wait anywhere on their path
        } else {
            if (lane == 0) { wsv[0] = v1; wsi[0] = i1; wev[0] = v2; wei[0] = i2; }
            mbar_wait_acq_cluster(&mbar, 0u);        // all lanes acquire-wait (7 arrivals)
            __syncwarp();                            // order lane0's local slot store
            float fv1 = (lane < 8) ? wsv[lane] : NEG;
            int   fi1 = (lane < 8) ? wsi[lane] : 0x7fffffff;
            float fv2 = (lane < 8) ? wev[lane] : NEG;
            int   fi2 = (lane < 8) ? wei[lane] : 0x7fffffff;
            #pragma unroll
            for (int o = 4; o; o >>= 1) {
                float ov = __shfl_xor_sync(0xffffffffu, fv1, o);
                int   oi = __shfl_xor_sync(0xffffffffu, fi1, o);
                if (ov > fv1 || (ov == fv1 && oi < fi1)) { fv1 = ov; fi1 = oi; }
                float ov2 = __shfl_xor_sync(0xffffffffu, fv2, o);
                int   oi2 = __shfl_xor_sync(0xffffffffu, fi2, o);
                if (ov2 > fv2 || (ov2 == fv2 && oi2 < fi2)) { fv2 = ov2; fi2 = oi2; }
            }
            if (lane == 0) {
                out[2 * BATCH * SEQ + row]         = (float)fi1;
                out[2 * BATCH * SEQ + BATCH + row] = (float)fi2;
            }
        }
    }
}

extern "C" void kernel_launch(void* const* d_in, const int* in_sizes, int n_in,
                              void* d_out, int out_size) {
    const float* start_logits = (const float*)d_in[0];
    const float* end_logits   = (const float*)d_in[1];
    float* out = (float*)d_out;
    pred_head_mb<<<BATCH * RANKS, NTC>>>(start_logits, end_logits, out);
}